// round 1
// baseline (speedup 1.0000x reference)
#include <cuda_runtime.h>
#include <math.h>

// ---------------- problem constants ----------------
#define NN 50000
#define EE 800000
#define HC 128          // HEADS * C_OUT
#define NSLOT (EE + NN) // edges + self loops
#define NEG_SLOPE 0.2f
#define BN_EPS 1e-5f
#define NB_SCAN ((NN + 255) / 256)   // 196

// ---------------- device-global scratch (no allocs allowed) ----------------
__device__ int    g_is64;
__device__ int    g_deg[NN];
__device__ int    g_cursor[NN];
__device__ float  g_wsum[NN];
__device__ float  g_loopw[NN];
__device__ int    g_rowstart[NN + 1];
__device__ int    g_part[256];
__device__ int    g_csrc[NSLOT];
__device__ float  g_cw[NSLOT];
__device__ float  g_xl[NN * HC];
__device__ float  g_xr[NN * HC];
__device__ float  g_h1[NN * HC];    // raw GAT1 output
__device__ float  g_h1a[NN * HC];   // after BN + ELU
__device__ double g_bnsum[HC], g_bnsq[HC];
__device__ float  g_mu[HC], g_inv[HC];

// ---------------- helpers ----------------
// edge_index may arrive as int64 (reference asks for it) or int32 (JAX default
// x64-disabled silently downcasts). Detect on device: for int64 little-endian,
// every odd 32-bit word is a zero high word (values < 2^31).
__device__ __forceinline__ void load_edge(const int* __restrict__ ei, int e, int E,
                                          int& s, int& d) {
    if (g_is64) { s = ei[2 * e]; d = ei[2 * (E + e)]; }
    else        { s = ei[e];     d = ei[E + e]; }
}

__global__ void detect_kernel(const int* __restrict__ ei) {
    if (threadIdx.x == 0) {
        int z = 0;
        #pragma unroll
        for (int j = 1; j < 64; j += 2) z |= ei[j];
        g_is64 = (z == 0) ? 1 : 0;
    }
}

__global__ void zero_kernel() {
    int i = blockIdx.x * blockDim.x + threadIdx.x;
    if (i < NN) { g_deg[i] = 0; g_wsum[i] = 0.f; g_cursor[i] = 0; }
    if (i < HC) { g_bnsum[i] = 0.0; g_bnsq[i] = 0.0; }
}

__global__ void deg_kernel(const int* __restrict__ ei, const float* __restrict__ ew, int E) {
    int e = blockIdx.x * blockDim.x + threadIdx.x;
    if (e >= E) return;
    int s, d; load_edge(ei, e, E, s, d);
    atomicAdd(&g_deg[d], 1);
    atomicAdd(&g_wsum[d], ew[e]);
}

__global__ void loopw_kernel(int n) {
    int i = blockIdx.x * blockDim.x + threadIdx.x;
    if (i < n) g_loopw[i] = g_wsum[i] / fmaxf((float)g_deg[i], 1.f);
}

// -------- 3-kernel exclusive scan over counts = deg[i] + 1 --------
__global__ void scan_part(int n) {
    __shared__ int sm[256];
    int tid = threadIdx.x;
    int i = blockIdx.x * 256 + tid;
    int v = (i < n) ? (g_deg[i] + 1) : 0;
    sm[tid] = v; __syncthreads();
    for (int off = 128; off > 0; off >>= 1) {
        if (tid < off) sm[tid] += sm[tid + off];
        __syncthreads();
    }
    if (tid == 0) g_part[blockIdx.x] = sm[0];
}

__global__ void scan_mid(int nb, int total) {
    __shared__ int sm[256];
    int tid = threadIdx.x;
    int v = (tid < nb) ? g_part[tid] : 0;
    sm[tid] = v; __syncthreads();
    for (int off = 1; off < 256; off <<= 1) {
        int t = (tid >= off) ? sm[tid - off] : 0;
        __syncthreads();
        sm[tid] += t;
        __syncthreads();
    }
    if (tid < nb) g_part[tid] = sm[tid] - v;   // exclusive
    if (tid == 0) g_rowstart[NN] = total;
}

__global__ void scan_final(int n) {
    __shared__ int sm[256];
    int tid = threadIdx.x;
    int i = blockIdx.x * 256 + tid;
    int v = (i < n) ? (g_deg[i] + 1) : 0;
    sm[tid] = v; __syncthreads();
    for (int off = 1; off < 256; off <<= 1) {
        int t = (tid >= off) ? sm[tid - off] : 0;
        __syncthreads();
        sm[tid] += t;
        __syncthreads();
    }
    if (i < n) g_rowstart[i] = g_part[blockIdx.x] + sm[tid] - v;   // exclusive
}

__global__ void csr_fill(const int* __restrict__ ei, const float* __restrict__ ew, int E) {
    int e = blockIdx.x * blockDim.x + threadIdx.x;
    if (e >= E) return;
    int s, d; load_edge(ei, e, E, s, d);
    int pos = atomicAdd(&g_cursor[d], 1);
    int slot = g_rowstart[d] + pos;
    g_csrc[slot] = s;
    g_cw[slot]   = ew[e];
}

__global__ void self_fill(int n) {
    int i = blockIdx.x * blockDim.x + threadIdx.x;
    if (i >= n) return;
    int slot = g_rowstart[i + 1] - 1;  // last slot of node i's segment
    g_csrc[slot] = i;
    g_cw[slot]   = g_loopw[i];
}

// -------- SGEMM: O[M,128] = A[M,128] @ W[128,128] + b, dual-W via gridDim.z --------
// BM=BN=128, BK=8, 8x8 microtiles, 256 threads.
__global__ __launch_bounds__(256) void sgemm_dual(
    const float* __restrict__ Aext,
    const float* __restrict__ W0, const float* __restrict__ b0,
    const float* __restrict__ W1, const float* __restrict__ b1,
    int M, int useH1a)
{
    const float* __restrict__ A    = useH1a ? g_h1a : Aext;
    const float* __restrict__ W    = blockIdx.z ? W1 : W0;
    const float* __restrict__ bias = blockIdx.z ? b1 : b0;
    float* __restrict__ O          = blockIdx.z ? g_xr : g_xl;

    __shared__ float As[8][128];  // [k][row]
    __shared__ float Bs[8][128];  // [k][col]

    int tid = threadIdx.x;
    int row0 = blockIdx.x * 128;
    int ty = tid / 16, tx = tid % 16;

    int a_r = tid >> 1;            // 0..127
    int a_c = (tid & 1) * 4;       // 0 or 4
    int b_r = tid >> 5;            // 0..7
    int b_c = (tid & 31) * 4;      // 0..124
    bool a_ok = (row0 + a_r) < M;
    const float* Aptr = A + (size_t)(row0 + a_r) * HC + a_c;

    float acc[8][8];
    #pragma unroll
    for (int i = 0; i < 8; i++)
        #pragma unroll
        for (int j = 0; j < 8; j++) acc[i][j] = 0.f;

    for (int k0 = 0; k0 < 128; k0 += 8) {
        float4 av = a_ok ? *(const float4*)(Aptr + k0) : make_float4(0.f, 0.f, 0.f, 0.f);
        float4 bv = *(const float4*)(W + (k0 + b_r) * 128 + b_c);
        __syncthreads();
        As[a_c + 0][a_r] = av.x; As[a_c + 1][a_r] = av.y;
        As[a_c + 2][a_r] = av.z; As[a_c + 3][a_r] = av.w;
        *(float4*)&Bs[b_r][b_c] = bv;
        __syncthreads();
        #pragma unroll
        for (int k = 0; k < 8; k++) {
            float ra[8], rb[8];
            #pragma unroll
            for (int i = 0; i < 8; i++) ra[i] = As[k][ty * 8 + i];
            #pragma unroll
            for (int j = 0; j < 8; j++) rb[j] = Bs[k][tx * 8 + j];
            #pragma unroll
            for (int i = 0; i < 8; i++)
                #pragma unroll
                for (int j = 0; j < 8; j++)
                    acc[i][j] = fmaf(ra[i], rb[j], acc[i][j]);
        }
    }

    #pragma unroll
    for (int i = 0; i < 8; i++) {
        int r = row0 + ty * 8 + i;
        if (r < M) {
            #pragma unroll
            for (int j = 0; j < 8; j++) acc[i][j] += __ldg(bias + tx * 8 + j);
            float4 v0 = make_float4(acc[i][0], acc[i][1], acc[i][2], acc[i][3]);
            float4 v1 = make_float4(acc[i][4], acc[i][5], acc[i][6], acc[i][7]);
            *(float4*)(O + (size_t)r * HC + tx * 8)     = v0;
            *(float4*)(O + (size_t)r * HC + tx * 8 + 4) = v1;
        }
    }
}

// -------- GATv2 aggregation: one warp per (node, head), lane = channel --------
// Online softmax over incoming CSR edges (includes self loop). No atomics.
__global__ __launch_bounds__(128) void gat_agg(
    const float* __restrict__ We, const float* __restrict__ att,
    const float* __restrict__ bias,
    const float* __restrict__ emb, float* __restrict__ outFinal,
    int mode, int n)
{
    int node = blockIdx.x;
    if (node >= n) return;
    int h = threadIdx.x >> 5;
    int c = threadIdx.x & 31;
    int col = (h << 5) | c;

    float att_v = __ldg(att + col);
    float we_v  = __ldg(We + col);
    float xr_v  = g_xr[(size_t)node * HC + col];
    int start = g_rowstart[node], end = g_rowstart[node + 1];

    float m = -INFINITY, s = 0.f, acc = 0.f;
    for (int i = start; i < end; ++i) {
        int   src = g_csrc[i];
        float w   = g_cw[i];
        float xlj = __ldg(g_xl + (size_t)src * HC + col);
        float t = fmaf(w, we_v, xlj + xr_v);
        t = (t > 0.f) ? t : NEG_SLOPE * t;
        float l = att_v * t;
        l += __shfl_xor_sync(0xffffffffu, l, 16);
        l += __shfl_xor_sync(0xffffffffu, l, 8);
        l += __shfl_xor_sync(0xffffffffu, l, 4);
        l += __shfl_xor_sync(0xffffffffu, l, 2);
        l += __shfl_xor_sync(0xffffffffu, l, 1);
        float nm = fmaxf(m, l);
        float sc = __expf(m - nm);   // first iter: exp(-inf) = 0
        float p  = __expf(l - nm);
        s   = fmaf(s, sc, p);
        acc = fmaf(acc, sc, p * xlj);
        m = nm;
    }
    float v = acc / s + __ldg(bias + col);
    size_t idx = (size_t)node * HC + col;
    if (mode) {
        outFinal[idx] = (emb[idx] + g_h1a[idx] + v) * (1.f / 3.f);
    } else {
        g_h1[idx] = v;
    }
}

// -------- BatchNorm (training-style stats) + ELU --------
__global__ __launch_bounds__(128) void bn_stats(int n) {
    int c = threadIdx.x;
    float s = 0.f, q = 0.f;
    for (int r = blockIdx.x; r < n; r += gridDim.x) {
        float v = g_h1[(size_t)r * HC + c];
        s += v; q += v * v;
    }
    atomicAdd(&g_bnsum[c], (double)s);
    atomicAdd(&g_bnsq[c], (double)q);
}

__global__ void bn_fin(int n) {
    int c = threadIdx.x;
    double mu = g_bnsum[c] / n;
    double var = g_bnsq[c] / n - mu * mu;
    g_mu[c]  = (float)mu;
    g_inv[c] = rsqrtf((float)var + BN_EPS);
}

__global__ void bn_apply(const float* __restrict__ gamma, const float* __restrict__ beta, int n) {
    int idx = blockIdx.x * blockDim.x + threadIdx.x;
    if (idx >= n * HC) return;
    int c = idx & (HC - 1);
    float v = g_h1[idx];
    v = fmaf(gamma[c] * (v - g_mu[c]), g_inv[c], beta[c]);
    g_h1a[idx] = (v > 0.f) ? v : expm1f(v);
}

// ---------------- launch ----------------
extern "C" void kernel_launch(void* const* d_in, const int* in_sizes, int n_in,
                              void* d_out, int out_size) {
    const float* emb   = (const float*)d_in[0];
    const int*   ei    = (const int*)d_in[1];   // int32 or int64 (detected)
    const float* ew    = (const float*)d_in[2];
    const float* Wl1   = (const float*)d_in[3];
    const float* bl1   = (const float*)d_in[4];
    const float* Wr1   = (const float*)d_in[5];
    const float* br1   = (const float*)d_in[6];
    const float* We1   = (const float*)d_in[7];
    const float* att1  = (const float*)d_in[8];
    const float* bias1 = (const float*)d_in[9];
    const float* gamma1= (const float*)d_in[10];
    const float* beta1 = (const float*)d_in[11];
    const float* Wl2   = (const float*)d_in[12];
    const float* bl2   = (const float*)d_in[13];
    const float* Wr2   = (const float*)d_in[14];
    const float* br2   = (const float*)d_in[15];
    const float* We2   = (const float*)d_in[16];
    const float* att2  = (const float*)d_in[17];
    const float* bias2 = (const float*)d_in[18];
    float* out = (float*)d_out;

    const int n = in_sizes[0] / HC;   // 50000
    const int E = in_sizes[2];        // 800000

    // preprocessing
    zero_kernel<<<(NN + 255) / 256, 256>>>();
    detect_kernel<<<1, 32>>>(ei);
    deg_kernel<<<(E + 255) / 256, 256>>>(ei, ew, E);
    loopw_kernel<<<(n + 255) / 256, 256>>>(n);
    scan_part<<<NB_SCAN, 256>>>(n);
    scan_mid<<<1, 256>>>(NB_SCAN, E + n);
    scan_final<<<NB_SCAN, 256>>>(n);
    csr_fill<<<(E + 255) / 256, 256>>>(ei, ew, E);
    self_fill<<<(n + 255) / 256, 256>>>(n);

    dim3 ggrid((n + 127) / 128, 1, 2);

    // layer 1
    sgemm_dual<<<ggrid, 256>>>(emb, Wl1, bl1, Wr1, br1, n, 0);
    gat_agg<<<n, 128>>>(We1, att1, bias1, nullptr, nullptr, 0, n);
    bn_stats<<<512, 128>>>(n);
    bn_fin<<<1, 128>>>(n);
    bn_apply<<<(n * HC + 255) / 256, 256>>>(gamma1, beta1, n);

    // layer 2 (+ fused final combine)
    sgemm_dual<<<ggrid, 256>>>(nullptr, Wl2, bl2, Wr2, br2, n, 1);
    gat_agg<<<n, 128>>>(We2, att2, bias2, emb, out, 1, n);
}